// round 13
// baseline (speedup 1.0000x reference)
#include <cuda_runtime.h>
#include <cuda_bf16.h>
#include <math.h>

#define B    32
#define CDIM 128
#define NSP  4096
#define HEADS 4
#define DH   32
#define EPS  1e-5f

typedef unsigned long long u64;
typedef unsigned int u32;

// ---------------- FFMA-only exp ----------------
__device__ __forceinline__ float exp_poly(float x) {
    float y = x * 1.4426950408889634f;
    float z = y + 12582912.0f;
    int   zb = __float_as_int(z);
    float n = z - 12582912.0f;
    float f = y - n;
    float p = 0.0096180f;
    p = fmaf(p, f, 0.0555041f);
    p = fmaf(p, f, 0.2402265f);
    p = fmaf(p, f, 0.6931472f);
    p = fmaf(p, f, 1.0f);
    return __int_as_float(__float_as_int(p) + (zb << 23));
}
__device__ __forceinline__ float exp_sel(float x, bool poly) {
    return poly ? exp_poly(x) : __expf(x);
}

// ---------------- mma.sync / ldmatrix wrappers ----------------
__device__ __forceinline__ void ldm4(u32* d, u32 addr) {
    asm volatile("ldmatrix.sync.aligned.m8n8.x4.shared.b16 {%0,%1,%2,%3},[%4];"
                 : "=r"(d[0]), "=r"(d[1]), "=r"(d[2]), "=r"(d[3]) : "r"(addr));
}
__device__ __forceinline__ void mma16816(float* c, const u32* a, u32 b0, u32 b1) {
    asm volatile("mma.sync.aligned.m16n8k16.row.col.f32.bf16.bf16.f32 "
                 "{%0,%1,%2,%3},{%4,%5,%6,%7},{%8,%9},{%0,%1,%2,%3};"
                 : "+f"(c[0]), "+f"(c[1]), "+f"(c[2]), "+f"(c[3])
                 : "r"(a[0]), "r"(a[1]), "r"(a[2]), "r"(a[3]), "r"(b0), "r"(b1));
}
__device__ __forceinline__ void mma16832s8(int* c, const u32* a, u32 b0, u32 b1) {
    asm volatile("mma.sync.aligned.m16n8k32.row.col.s32.s8.s8.s32 "
                 "{%0,%1,%2,%3},{%4,%5,%6,%7},{%8,%9},{%0,%1,%2,%3};"
                 : "+r"(c[0]), "+r"(c[1]), "+r"(c[2]), "+r"(c[3])
                 : "r"(a[0]), "r"(a[1]), "r"(a[2]), "r"(a[3]), "r"(b0), "r"(b1));
}

// cp.async helpers
#define CPA16(saddr, gptr) \
    asm volatile("cp.async.cg.shared.global [%0],[%1],16;" :: "r"(saddr), "l"(gptr) : "memory")
#define CPA_COMMIT() asm volatile("cp.async.commit_group;" ::: "memory")
#define CPA_WAIT0()  asm volatile("cp.async.wait_group 0;" ::: "memory")

// split a float4 into bf16x2 hi/lo packed words
__device__ __forceinline__ void split4(float4 v, u32& h0, u32& h1, u32& l0, u32& l1) {
    asm("cvt.rn.bf16x2.f32 %0,%1,%2;" : "=r"(h0) : "f"(v.y), "f"(v.x));
    asm("cvt.rn.bf16x2.f32 %0,%1,%2;" : "=r"(h1) : "f"(v.w), "f"(v.z));
    float r0 = v.x - __int_as_float((int)(h0 << 16));
    float r1 = v.y - __int_as_float((int)(h0 & 0xFFFF0000u));
    float r2 = v.z - __int_as_float((int)(h1 << 16));
    float r3 = v.w - __int_as_float((int)(h1 & 0xFFFF0000u));
    asm("cvt.rn.bf16x2.f32 %0,%1,%2;" : "=r"(l0) : "f"(r1), "f"(r0));
    asm("cvt.rn.bf16x2.f32 %0,%1,%2;" : "=r"(l1) : "f"(r3), "f"(r2));
}
__device__ __forceinline__ uint2 pack2(float x, float y) {
    u32 h, lo;
    asm("cvt.rn.bf16x2.f32 %0,%1,%2;" : "=r"(h) : "f"(y), "f"(x));
    float rx = x - __int_as_float((int)(h << 16));
    float ry = y - __int_as_float((int)(h & 0xFFFF0000u));
    asm("cvt.rn.bf16x2.f32 %0,%1,%2;" : "=r"(lo) : "f"(ry), "f"(rx));
    return make_uint2(h, lo);
}
__device__ __forceinline__ u32 pack4i(int a, int b, int c, int d) {
    return (u32)(a & 0xFF) | ((u32)(b & 0xFF) << 8) | ((u32)(c & 0xFF) << 16)
         | ((u32)d << 24);
}

// ---------------- scratch ----------------
__device__ float g_q[(size_t)B * CDIM * NSP];                 // exp(q) fp32
__device__ __align__(16) uint2 g_kp[(size_t)B * CDIM * 2048]; // exp(k) (hi,lo)
__device__ __align__(16) uint2 g_vp[(size_t)B * CDIM * 2048]; // v (hi,lo)
__device__ float g_Sp[(size_t)B * HEADS * 4 * DH * DH];
__device__ float g_Zp64[(size_t)B * 64 * 2 * 128];
__device__ float g_ctx[(size_t)B * 4096];
__device__ __align__(16) u32 g_Wqh[384 * 32];                 // int8 hi W
__device__ __align__(16) u32 g_Wql[384 * 32];                 // int8 lo W
__device__ float g_sw[384];                                   // per-row W scale
__device__ __align__(16) unsigned short g_Mbh[(size_t)B * 16384];
__device__ __align__(16) unsigned short g_Mbl[(size_t)B * 16384];

// ---------------------------------------------------------------------------
// Kernel 0: quantize Wqkv rows to two-level int8 (per-row scale).
// grid 48 x 256 = 384 warps, one row each.
// ---------------------------------------------------------------------------
__global__ void k_quantW(const float* __restrict__ W) {
    int wg = blockIdx.x * 8 + (threadIdx.x >> 5);
    int l = threadIdx.x & 31;
    if (wg >= 384) return;
    float4 v = *(const float4*)(W + wg * 128 + l * 4);
    float m = fmaxf(fmaxf(fabsf(v.x), fabsf(v.y)), fmaxf(fabsf(v.z), fabsf(v.w)));
#pragma unroll
    for (int s = 1; s < 32; s <<= 1) m = fmaxf(m, __shfl_xor_sync(0xffffffffu, m, s));
    m = fmaxf(m, 1e-30f);
    float rinv = 127.f / m;
    int h[4], lo[4];
    float f[4] = {v.x, v.y, v.z, v.w};
#pragma unroll
    for (int j = 0; j < 4; j++) {
        float t = f[j] * rinv;
        float hf = rintf(t);
        h[j] = (int)hf;
        lo[j] = (int)rintf((t - hf) * 254.f);
    }
    g_Wqh[wg * 32 + l] = pack4i(h[0], h[1], h[2], h[3]);
    g_Wql[wg * 32 + l] = pack4i(lo[0], lo[1], lo[2], lo[3]);
    if (l == 0) g_sw[wg] = m * (1.f / 127.f);
}

// ---------------------------------------------------------------------------
// Kernel 1: qkv = Wqkv @ x via two-level INT8 IMMA (m16n8k32.s8).
// B = x quantized per-column (two-level); A = pre-quantized W (per-row).
// acc = sw*sx*(HH + (HL+LH)/254). Fused epilogue unchanged (exp/Z/pack).
// grid = (64 n-tiles, 32 batches), 256 threads.
// smem: Bh/Bl int8 [64n][144B]; Ah/Al int8 [128o][144B] (stage overlays Ah).
// ---------------------------------------------------------------------------
#define SMEM_K1 56832
__global__ void __launch_bounds__(256, 2) k_gemm_qkv(const float* __restrict__ x) {
    extern __shared__ char sm[];
    const u32 sbase = (u32)__cvta_generic_to_shared(sm);
    const u32 oBh = 0, oBl = 9216, oAh = 18432, oAl = 36864;
    float* sxs = (float*)(sm + 55296);   // 64 col scales
    float* sxi = (float*)(sm + 55552);   // 64 col inverse scales
    float* zm  = (float*)(sm + 55808);   // 4*64 col-max partials
    float* stage = (float*)(sm + oAh);
    const int t = blockIdx.x, b = blockIdx.y;
    const int tid = threadIdx.x;
    const float* xb = x + (size_t)b * CDIM * NSP + t * 64;

    // phase 1: x tile [128k][64n] -> fp32 stage stride 68
#pragma unroll
    for (int it = 0; it < 8; it++) {
        int u = tid + it * 256;
        int k = u >> 4, nc = (u & 15) << 2;
        float4 v = *(const float4*)(xb + (size_t)k * NSP + nc);
        *(float4*)(stage + k * 68 + nc) = v;
    }
    __syncthreads();

    // phase 1b: per-column max
    {
        int n = tid & 63, qt = tid >> 6;
        float m = 0.f;
#pragma unroll
        for (int kk = 0; kk < 32; kk++)
            m = fmaxf(m, fabsf(stage[(qt * 32 + kk) * 68 + n]));
        zm[qt * 64 + n] = m;
    }
    __syncthreads();
    if (tid < 64) {
        float m = fmaxf(fmaxf(zm[tid], zm[64 + tid]), fmaxf(zm[128 + tid], zm[192 + tid]));
        m = fmaxf(m, 1e-30f);
        sxs[tid] = m * (1.f / 127.f);
        sxi[tid] = 127.f / m;
    }
    __syncthreads();

    // phase 2: transpose-quantize to int8 hi/lo [n][k bytes] stride 144
#pragma unroll
    for (int it = 0; it < 4; it++) {
        int v = tid + it * 256;
        int n = v & 63, k8 = v >> 6;
        float rinv = sxi[n];
        int h[8], lo[8];
#pragma unroll
        for (int j = 0; j < 8; j++) {
            float tt = stage[(k8 * 8 + j) * 68 + n] * rinv;
            float hf = rintf(tt);
            h[j] = (int)hf;
            lo[j] = (int)rintf((tt - hf) * 254.f);
        }
        u32 off = n * 144 + k8 * 8;
        *(uint2*)(sm + oBh + off) =
            make_uint2(pack4i(h[0], h[1], h[2], h[3]), pack4i(h[4], h[5], h[6], h[7]));
        *(uint2*)(sm + oBl + off) =
            make_uint2(pack4i(lo[0], lo[1], lo[2], lo[3]), pack4i(lo[4], lo[5], lo[6], lo[7]));
    }
    __syncthreads();

    const int l = tid & 31, wid = tid >> 5;
    const int wm = (wid & 3) * 32;
    const int nh = (wid >> 2) * 32;
    const u32 aoff = (u32)((wm + (l & 15)) * 144 + (l >> 4) * 16);
    const u32 boff = (u32)((nh + (l & 7) + ((l >> 4) << 3)) * 144 + (((l >> 3) & 1) << 4));

    for (int rb = 0; rb < 3; rb++) {
        // load A = int8 W rows rb*128..+127 into smem stride 144
        {
            const uint4* gh = (const uint4*)g_Wqh + rb * 1024;
            const uint4* gl = (const uint4*)g_Wql + rb * 1024;
#pragma unroll
            for (int it = 0; it < 4; it++) {
                int u = tid + it * 256;
                int r = u >> 3, c = u & 7;
                u32 off = r * 144 + c * 16;
                *(uint4*)(sm + oAh + off) = gh[u];
                *(uint4*)(sm + oAl + off) = gl[u];
            }
        }
        __syncthreads();

        int accH[2][4][4], accX[2][4][4];
#pragma unroll
        for (int mt = 0; mt < 2; mt++)
#pragma unroll
            for (int nt = 0; nt < 4; nt++)
#pragma unroll
                for (int q = 0; q < 4; q++) { accH[mt][nt][q] = 0; accX[mt][nt][q] = 0; }

#pragma unroll
        for (int kc = 0; kc < 4; kc++) {
            u32 ah[2][4], al_[2][4], bh_[2][4], bl_[2][4];
#pragma unroll
            for (int mt = 0; mt < 2; mt++) {
                u32 o = aoff + mt * (16 * 144) + kc * 32;
                ldm4(ah[mt],  sbase + oAh + o);
                ldm4(al_[mt], sbase + oAl + o);
            }
#pragma unroll
            for (int p = 0; p < 2; p++) {
                u32 o = boff + p * (16 * 144) + kc * 32;
                ldm4(bh_[p], sbase + oBh + o);
                ldm4(bl_[p], sbase + oBl + o);
            }
#pragma unroll
            for (int mt = 0; mt < 2; mt++)
#pragma unroll
                for (int nt = 0; nt < 4; nt++) {
                    int p = nt >> 1, q = (nt & 1) * 2;
                    mma16832s8(accH[mt][nt], ah[mt],  bh_[p][q], bh_[p][q + 1]);
                    mma16832s8(accX[mt][nt], ah[mt],  bl_[p][q], bl_[p][q + 1]);
                    mma16832s8(accX[mt][nt], al_[mt], bh_[p][q], bh_[p][q + 1]);
                }
        }

        // dequantize to float
        float facc[2][4][4];
#pragma unroll
        for (int mt = 0; mt < 2; mt++)
#pragma unroll
            for (int rh = 0; rh < 2; rh++) {
                int row = wm + mt * 16 + (l >> 2) + rh * 8;
                float swv = __ldg(g_sw + rb * 128 + row);
#pragma unroll
                for (int nt = 0; nt < 4; nt++) {
                    int col = nh + nt * 8 + (l & 3) * 2;
#pragma unroll
                    for (int q = 0; q < 2; q++) {
                        float s = swv * sxs[col + q];
                        facc[mt][nt][rh * 2 + q] =
                            s * ((float)accH[mt][nt][rh * 2 + q] +
                                 (float)accX[mt][nt][rh * 2 + q] * (1.f / 254.f));
                    }
                }
            }

        if (rb == 0) {
#pragma unroll
            for (int mt = 0; mt < 2; mt++)
#pragma unroll
                for (int rh = 0; rh < 2; rh++) {
                    int row = wm + mt * 16 + (l >> 2) + rh * 8;
                    float* outp = g_q + ((size_t)b * CDIM + row) * NSP + t * 64;
#pragma unroll
                    for (int nt = 0; nt < 4; nt++) {
                        bool up = (mt == 0) || (rh == 0 && nt < 2);
                        float2 o2;
                        o2.x = exp_sel(facc[mt][nt][rh * 2 + 0], up);
                        o2.y = exp_sel(facc[mt][nt][rh * 2 + 1], up);
                        *(float2*)(outp + nh + nt * 8 + (l & 3) * 2) = o2;
                    }
                }
        } else if (rb == 1) {
#pragma unroll
            for (int mt = 0; mt < 2; mt++)
#pragma unroll
                for (int rh = 0; rh < 2; rh++)
#pragma unroll
                    for (int nt = 0; nt < 4; nt++) {
                        bool up = (mt == 0) || (rh == 0 && nt < 2);
                        facc[mt][nt][rh * 2 + 0] = exp_sel(facc[mt][nt][rh * 2 + 0], up);
                        facc[mt][nt][rh * 2 + 1] = exp_sel(facc[mt][nt][rh * 2 + 1], up);
                    }
#pragma unroll
            for (int mt = 0; mt < 2; mt++)
#pragma unroll
                for (int rh = 0; rh < 2; rh++) {
                    int row = wm + mt * 16 + (l >> 2) + rh * 8;
                    float s = 0.f;
#pragma unroll
                    for (int nt = 0; nt < 4; nt++)
                        s += facc[mt][nt][rh * 2 + 0] + facc[mt][nt][rh * 2 + 1];
                    s += __shfl_xor_sync(0xffffffffu, s, 1);
                    s += __shfl_xor_sync(0xffffffffu, s, 2);
                    if ((l & 3) == 0)
                        g_Zp64[((size_t)b * 64 + t) * 256 + (wid >> 2) * 128 + row] = s;
                }
#pragma unroll
            for (int mt = 0; mt < 2; mt++)
#pragma unroll
                for (int rh = 0; rh < 2; rh++) {
                    int row = wm + mt * 16 + (l >> 2) + rh * 8;
                    uint2* kr = g_kp + ((size_t)b * CDIM + row) * 2048 + t * 32 + (nh >> 1);
#pragma unroll
                    for (int nt = 0; nt < 4; nt++)
                        kr[nt * 4 + (l & 3)] =
                            pack2(facc[mt][nt][rh * 2 + 0], facc[mt][nt][rh * 2 + 1]);
                }
        } else {
#pragma unroll
            for (int mt = 0; mt < 2; mt++)
#pragma unroll
                for (int rh = 0; rh < 2; rh++) {
                    int row = wm + mt * 16 + (l >> 2) + rh * 8;
                    uint2* vr = g_vp + ((size_t)b * CDIM + row) * 2048 + t * 32 + (nh >> 1);
#pragma unroll
                    for (int nt = 0; nt < 4; nt++)
                        vr[nt * 4 + (l & 3)] =
                            pack2(facc[mt][nt][rh * 2 + 0], facc[mt][nt][rh * 2 + 1]);
                }
        }
        __syncthreads();
    }
}

// ---------------------------------------------------------------------------
// Kernel 2: Sp = sum_n exp(k)*v^T via split-bf16 mma (unchanged from R12)
// ---------------------------------------------------------------------------
__global__ void __launch_bounds__(256) k_reduce_kv() {
    __shared__ __align__(16) char sm2[34816 + 4224];
    const u32 sbase = (u32)__cvta_generic_to_shared(sm2);
    const u32 oAh = 0, oAl = 8704, oBh = 17408, oBl = 26112;
    float* sbuf = (float*)(sm2 + 34816);
    const int h = blockIdx.x, p = blockIdx.y, b = blockIdx.z;
    const int tid = threadIdx.x;
    const int l = tid & 31, w = tid >> 5;

    const int mt = w & 1, np = (w >> 1) & 1, kh = w >> 2;
    const u32 aoff = (u32)((mt * 16 + (l & 15)) * 272 + (l >> 4) * 16);
    const u32 boff = (u32)((np * 16 + (l & 7) + ((l >> 4) << 3)) * 272 + (((l >> 3) & 1) << 4));

    const uint4* kbase[4];
    const uint4* vbase[4];
#pragma unroll
    for (int i = 0; i < 4; i++) {
        kbase[i] = (const uint4*)(g_kp + ((size_t)b * CDIM + h * 32 + w + i * 8) * 2048)
                   + p * 256 + l;
        vbase[i] = (const uint4*)(g_vp + ((size_t)b * CDIM + h * 32 + w + i * 8) * 2048)
                   + p * 256 + l;
    }

    float acc[2][4];
#pragma unroll
    for (int g = 0; g < 2; g++)
#pragma unroll
        for (int q = 0; q < 4; q++) acc[g][q] = 0.f;

    uint4 kreg[4], vreg[4];
#pragma unroll
    for (int i = 0; i < 4; i++) { kreg[i] = kbase[i][0]; vreg[i] = vbase[i][0]; }

    for (int ch = 0; ch < 8; ch++) {
        __syncthreads();
#pragma unroll
        for (int i = 0; i < 4; i++) {
            int d = w + i * 8;
            *(uint2*)(sm2 + oAh + d * 272 + l * 8) = make_uint2(kreg[i].x, kreg[i].z);
            *(uint2*)(sm2 + oAl + d * 272 + l * 8) = make_uint2(kreg[i].y, kreg[i].w);
            *(uint2*)(sm2 + oBh + d * 272 + l * 8) = make_uint2(vreg[i].x, vreg[i].z);
            *(uint2*)(sm2 + oBl + d * 272 + l * 8) = make_uint2(vreg[i].y, vreg[i].w);
        }
        __syncthreads();
        if (ch < 7) {
#pragma unroll
            for (int i = 0; i < 4; i++) {
                kreg[i] = kbase[i][(ch + 1) * 32];
                vreg[i] = vbase[i][(ch + 1) * 32];
            }
        }
#pragma unroll
        for (int kc2 = 0; kc2 < 4; kc2++) {
            int kc = kh * 4 + kc2;
            u32 ah[4], al_[4], bh_[4], bl_[4];
            ldm4(ah,  sbase + oAh + aoff + kc * 32);
            ldm4(al_, sbase + oAl + aoff + kc * 32);
            ldm4(bh_, sbase + oBh + boff + kc * 32);
            ldm4(bl_, sbase + oBl + boff + kc * 32);
#pragma unroll
            for (int g = 0; g < 2; g++) {
                mma16816(acc[g], ah,  bh_[g * 2], bh_[g * 2 + 1]);
                mma16816(acc[g], al_, bh_[g * 2], bh_[g * 2 + 1]);
                mma16816(acc[g], ah,  bl_[g * 2], bl_[g * 2 + 1]);
            }
        }
    }

    __syncthreads();
    if (kh == 0) {
#pragma unroll
        for (int g = 0; g < 2; g++)
#pragma unroll
            for (int rh = 0; rh < 2; rh++)
#pragma unroll
                for (int q = 0; q < 2; q++) {
                    int row = mt * 16 + (l >> 2) + rh * 8;
                    int col = np * 16 + g * 8 + (l & 3) * 2 + q;
                    sbuf[row * 33 + col] = acc[g][rh * 2 + q];
                }
    }
    __syncthreads();
    if (kh == 1) {
#pragma unroll
        for (int g = 0; g < 2; g++)
#pragma unroll
            for (int rh = 0; rh < 2; rh++)
#pragma unroll
                for (int q = 0; q < 2; q++) {
                    int row = mt * 16 + (l >> 2) + rh * 8;
                    int col = np * 16 + g * 8 + (l & 3) * 2 + q;
                    sbuf[row * 33 + col] += acc[g][rh * 2 + q];
                }
    }
    __syncthreads();
    float* Sp = g_Sp + (((size_t)(b * HEADS + h) * 4 + p) << 10);
#pragma unroll
    for (int i2 = 0; i2 < 4; i2++) {
        int idx = tid + i2 * 256;
        Sp[idx] = sbuf[(idx >> 5) * 33 + (idx & 31)];
    }
}

// ---------------------------------------------------------------------------
// Kernel 3a: ctx = (sum_p Sp)/Z  -> g_ctx (once per batch; parallel Z).
// ---------------------------------------------------------------------------
__global__ void __launch_bounds__(256) k_ctx() {
    __shared__ float zpart[256];
    __shared__ float zs[128];
    const int b = blockIdx.x;
    const int tid = threadIdx.x;
    {
        const float* zp = g_Zp64 + (size_t)b * 16384 + (tid >> 7) * 128 + (tid & 127);
        float z = 0.f;
#pragma unroll 8
        for (int s = 0; s < 64; s++) z += zp[(size_t)s * 256];
        zpart[tid] = z;
    }
    __syncthreads();
    if (tid < 128) zs[tid] = zpart[tid] + zpart[tid + 128];
    __syncthreads();
#pragma unroll
    for (int s2 = 0; s2 < 16; s2++) {
        int idx = tid + s2 * 256;
        int h = idx >> 10, d = (idx >> 5) & 31;
        float s = 0.f;
#pragma unroll
        for (int p = 0; p < 4; p++)
            s += g_Sp[(((size_t)(b * HEADS + h) * 4 + p) << 10) + (idx & 1023)];
        g_ctx[(size_t)b * 4096 + idx] = s / zs[h * 32 + d];
    }
}

// ---------------------------------------------------------------------------
// Kernel 3b: M_b = Wout∘ctx as bf16 hi/lo.  grid = (32, 8 o-slices).
// ---------------------------------------------------------------------------
__global__ void __launch_bounds__(256) k_M(const float* __restrict__ Wout) {
    __shared__ float ctxs[4 * 32 * 33];
    const int b = blockIdx.x;
    const int og = blockIdx.y;
    const int tid = threadIdx.x;
#pragma unroll
    for (int s2 = 0; s2 < 16; s2++) {
        int idx = tid + s2 * 256;
        int h = idx >> 10, d = (idx >> 5) & 31, e = idx & 31;
        ctxs[h * 1056 + d * 33 + e] = g_ctx[(size_t)b * 4096 + idx];
    }
    __syncthreads();
    unsigned short* Mh = g_Mbh + (size_t)b * 16384;
    unsigned short* Ml = g_Mbl + (size_t)b * 16384;
#pragma unroll
    for (int s8 = 0; s8 < 8; s8++) {
        int pidx = og * 2048 + tid + s8 * 256;
        int o = pidx >> 7, hd = pidx & 127;
        int h = hd >> 5, dd = hd & 31;
        const float* wrow = Wout + o * 128 + h * 32;
        const float* crow = ctxs + h * 1056 + dd * 33;
        float s = 0.f;
#pragma unroll
        for (int e = 0; e < 32; e++) s += __ldg(wrow + e) * crow[e];
        __nv_bfloat16 hb = __float2bfloat16(s);
        float hf = __bfloat162float(hb);
        Mh[pidx] = __bfloat16_as_ushort(hb);
        Ml[pidx] = __bfloat16_as_ushort(__float2bfloat16(s - hf));
    }
}

// ---------------------------------------------------------------------------
// Kernel 4: out = LayerNorm( M_b @ softmax_d(q) + bout )  (unchanged R12)
// ---------------------------------------------------------------------------
#define SMEM_K4 107008
__global__ void __launch_bounds__(256) k_out(const float* __restrict__ bout,
                                             const float* __restrict__ lnw,
                                             const float* __restrict__ lnb,
                                             float* __restrict__ out) {
    extern __shared__ char sm[];
    const u32 sbase = (u32)__cvta_generic_to_shared(sm);
    const u32 oBh = 0, oBl = 17408, oAh = 34816, oAl = 69632;
    float* stage = (float*)(sm + oAh);
    float* ssum  = (float*)(sm + 104448);
    float* red   = (float*)(sm + 105472);
    float* meanv = (float*)(sm + 106496);
    float* rstd  = (float*)(sm + 106752);
    const int t = blockIdx.x, b = blockIdx.y;
    const int tid = threadIdx.x;
    const float* qb = g_q + (size_t)b * CDIM * NSP + t * 64;

    {
        const uint4* gl = (const uint4*)(g_Mbl + (size_t)b * 16384);
#pragma unroll
        for (int it = 0; it < 8; it++) {
            int u = tid + it * 256;
            int r = u >> 4, c = u & 15;
            CPA16(sbase + oAl + r * 272 + c * 16, gl + u);
        }
        CPA_COMMIT();
    }

#pragma unroll
    for (int it = 0; it < 8; it++) {
        int u = tid + it * 256;
        int k = u >> 4, nc = (u & 15) << 2;
        float4 v = *(const float4*)(qb + (size_t)k * NSP + nc);
        *(float4*)(stage + k * 68 + nc) = v;
    }
    __syncthreads();

    {
        int n = tid & 63, hh = tid >> 6;
        float s = 0.f;
#pragma unroll
        for (int kk = 0; kk < 32; kk++) s += stage[(hh * 32 + kk) * 68 + n];
        ssum[hh * 64 + n] = 1.f / s;
    }
    __syncthreads();

#pragma unroll
    for (int it = 0; it < 4; it++) {
        int v = tid + it * 256;
        int n = v & 63, k8 = v >> 6;
        float rn_ = ssum[(k8 >> 2) * 64 + n];
        u32 hw[4], lw[4];
#pragma unroll
        for (int jj = 0; jj < 2; jj++) {
            float4 q4;
            q4.x = stage[(k8 * 8 + 4 * jj + 0) * 68 + n] * rn_;
            q4.y = stage[(k8 * 8 + 4 * jj + 1) * 68 + n] * rn_;
            q4.z = stage[(k8 * 8 + 4 * jj + 2) * 68 + n] * rn_;
            q4.w = stage[(k8 * 8 + 4 * jj + 3) * 68 + n] * rn_;
            split4(q4, hw[2 * jj], hw[2 * jj + 1], lw[2 * jj], lw[2 * jj + 1]);
        }
        u32 off = n * 272 + k8 * 16;
        *(uint4*)(sm + oBh + off) = make_uint4(hw[0], hw[1], hw[2], hw[3]);
        *(uint4*)(sm + oBl + off) = make_uint4(lw[0], lw[1], lw[2], lw[3]);
    }
    __syncthreads();

    {
        const uint4* gh = (const uint4*)(g_Mbh + (size_t)b * 16384);
#pragma unroll
        for (int it = 0; it < 8; it++) {
            int u = tid + it * 256;
            int r = u >> 4, c = u & 15;
            CPA16(sbase + oAh + r * 272 + c * 16, gh + u);
        }
        CPA_COMMIT();
        CPA_WAIT0();
    }
    __syncthreads();

    const int l = tid & 31, wid = tid >> 5;
    const int wm = (wid & 3) * 32;
    const int nh = (wid >> 2) * 32;
    const u32 aoff = (u32)((wm + (l & 15)) * 272 + (l >> 4) * 16);
    const u32 boff = (u32)((nh + (l & 7) + ((l >> 4) << 3)) * 272 + (((l >> 3) & 1) << 4));

    float acc[2][4][4];
#pragma unroll
    for (int mt = 0; mt < 2; mt++)
#pragma unroll
        for (int nt = 0; nt < 4; nt++)
#pragma unroll
            for (int q = 0; q < 4; q++) acc[mt][nt][q] = 0.f;

#pragma unroll
    for (int kc = 0; kc < 8; kc++) {
        u32 ah[2][4], al_[2][4], bhf[2][4], blf[2][4];
#pragma unroll
        for (int mt = 0; mt < 2; mt++) {
            u32 o = aoff + mt * (16 * 272) + kc * 32;
            ldm4(ah[mt],  sbase + oAh + o);
            ldm4(al_[mt], sbase + oAl + o);
        }
#pragma unroll
        for (int p = 0; p < 2; p++) {
            u32 o = boff + p * (16 * 272) + kc * 32;
            ldm4(bhf[p], sbase + oBh + o);
            ldm4(blf[p], sbase + oBl + o);
        }
#pragma unroll
        for (int mt = 0; mt < 2; mt++)
#pragma unroll
            for (int nt = 0; nt < 4; nt++) {
                int p = nt >> 1, q = (nt & 1) * 2;
                mma16816(acc[mt][nt], ah[mt],  bhf[p][q], bhf[p][q + 1]);
                mma16816(acc[mt][nt], al_[mt], bhf[p][q], bhf[p][q + 1]);
                mma16816(acc[mt][nt], ah[mt],  blf[p][q], blf[p][q + 1]);
            }
    }

#pragma unroll
    for (int mt = 0; mt < 2; mt++)
#pragma unroll
        for (int rh = 0; rh < 2; rh++) {
            float bo = __ldg(bout + wm + mt * 16 + (l >> 2) + rh * 8);
#pragma unroll
            for (int nt = 0; nt < 4; nt++) {
                acc[mt][nt][rh * 2 + 0] += bo;
                acc[mt][nt][rh * 2 + 1] += bo;
            }
        }

#pragma unroll
    for (int q = 0; q < 2; q++) {
#pragma unroll
        for (int nt = 0; nt < 4; nt++) {
            float cs = acc[0][nt][q] + acc[0][nt][2 + q] + acc[1][nt][q] + acc[1][nt][2 + q];
            cs += __shfl_xor_sync(0xffffffffu, cs, 4);
            cs += __shfl_xor_sync(0xffffffffu, cs, 8);
            cs += __shfl_xor_sync(0xffffffffu, cs, 16);
            if (l < 4) red[(wid & 3) * 64 + nh + nt * 8 + l * 2 + q] = cs;
        }
    }
    __syncthreads();
    if (tid < 64) {
        float s = red[tid] + red[64 + tid] + red[128 + tid] + red[192 + tid];
        meanv[tid] = s * (1.f / 128.f);
    }
    __syncthreads();
#pragma unroll
    for (int q = 0; q < 2; q++) {
#pragma unroll
        for (int nt = 0; nt < 4; nt++) {
            float cm = meanv[nh + nt * 8 + (l & 3) * 2 + q];
            float d0 = acc[0][nt][q] - cm, d1 = acc[0][nt][2 + q] - cm;
            float d2 = acc[1][nt][q] - cm, d3 = acc[1][nt][2 + q] - cm;
            float cs = d0 * d0 + d1 * d1 + d2 * d2 + d3 * d3;
            cs += __shfl_xor_sync(0xffffffffu, cs, 4);
            cs += __shfl_xor_sync(0xffffffffu, cs, 8);
            cs += __shfl_xor_sync(0xffffffffu, cs, 16);
            if (l < 4) red[(wid & 3) * 64 + nh + nt * 8 + l * 2 + q] = cs;
        }
    }
    __syncthreads();
    if (tid < 64) {
        float s = red[tid] + red[64 + tid] + red[128 + tid] + red[192 + tid];
        rstd[tid] = rsqrtf(s * (1.f / 128.f) + EPS);
    }
    __syncthreads();

#pragma unroll
    for (int mt = 0; mt < 2; mt++)
#pragma unroll
        for (int rh = 0; rh < 2; rh++) {
            int row = wm + mt * 16 + (l >> 2) + rh * 8;
            float lw = __ldg(lnw + row);
            float lb = __ldg(lnb + row);
#pragma unroll
            for (int nt = 0; nt < 4; nt++) {
                int col = nh + nt * 8 + (l & 3) * 2;
                float m0 = meanv[col], m1 = meanv[col + 1];
                float r0 = rstd[col], r1 = rstd[col + 1];
                float2 o2;
                o2.x = (acc[mt][nt][rh * 2 + 0] - m0) * r0 * lw + lb;
                o2.y = (acc[mt][nt][rh * 2 + 1] - m1) * r1 * lw + lb;
                *(float2*)(out + ((size_t)b * CDIM + row) * NSP + t * 64 + col) = o2;
            }
        }
}

// ---------------------------------------------------------------------------
extern "C" void kernel_launch(void* const* d_in, const int* in_sizes, int n_in,
                              void* d_out, int out_size) {
    const float* x    = (const float*)d_in[0];
    const float* Wqkv = (const float*)d_in[1];
    const float* Wout = (const float*)d_in[2];
    const float* bout = (const float*)d_in[3];
    const float* lnw  = (const float*)d_in[4];
    const float* lnb  = (const float*)d_in[5];
    float* out = (float*)d_out;

    cudaFuncSetAttribute(k_gemm_qkv, cudaFuncAttributeMaxDynamicSharedMemorySize, SMEM_K1);
    cudaFuncSetAttribute(k_out, cudaFuncAttributeMaxDynamicSharedMemorySize, SMEM_K4);

    k_quantW<<<48, 256>>>(Wqkv);
    k_gemm_qkv<<<dim3(64, B), 256, SMEM_K1>>>(x);
    k_reduce_kv<<<dim3(HEADS, 4, B), 256>>>();
    k_ctx<<<B, 256>>>();
    k_M<<<dim3(B, 8), 256>>>(Wout);
    k_out<<<dim3(64, B), 256, SMEM_K4>>>(bout, lnw, lnb, out);
}

// round 16
// speedup vs baseline: 1.5189x; 1.5189x over previous
#include <cuda_runtime.h>
#include <cuda_bf16.h>
#include <math.h>

#define B    32
#define CDIM 128
#define NSP  4096
#define HEADS 4
#define DH   32
#define EPS  1e-5f

typedef unsigned long long u64;
typedef unsigned int u32;

// ---------------- FFMA-only exp ----------------
__device__ __forceinline__ float exp_poly(float x) {
    float y = x * 1.4426950408889634f;
    float z = y + 12582912.0f;
    int   zb = __float_as_int(z);
    float n = z - 12582912.0f;
    float f = y - n;
    float p = 0.0096180f;
    p = fmaf(p, f, 0.0555041f);
    p = fmaf(p, f, 0.2402265f);
    p = fmaf(p, f, 0.6931472f);
    p = fmaf(p, f, 1.0f);
    return __int_as_float(__float_as_int(p) + (zb << 23));
}
__device__ __forceinline__ float exp_sel(float x, bool poly) {
    return poly ? exp_poly(x) : __expf(x);
}

// ---------------- mma.sync / ldmatrix wrappers ----------------
__device__ __forceinline__ void ldm4(u32* d, u32 addr) {
    asm volatile("ldmatrix.sync.aligned.m8n8.x4.shared.b16 {%0,%1,%2,%3},[%4];"
                 : "=r"(d[0]), "=r"(d[1]), "=r"(d[2]), "=r"(d[3]) : "r"(addr));
}
__device__ __forceinline__ void mma16816(float* c, const u32* a, u32 b0, u32 b1) {
    asm volatile("mma.sync.aligned.m16n8k16.row.col.f32.bf16.bf16.f32 "
                 "{%0,%1,%2,%3},{%4,%5,%6,%7},{%8,%9},{%0,%1,%2,%3};"
                 : "+f"(c[0]), "+f"(c[1]), "+f"(c[2]), "+f"(c[3])
                 : "r"(a[0]), "r"(a[1]), "r"(a[2]), "r"(a[3]), "r"(b0), "r"(b1));
}

// cp.async helpers
#define CPA16(saddr, gptr) \
    asm volatile("cp.async.cg.shared.global [%0],[%1],16;" :: "r"(saddr), "l"(gptr) : "memory")
#define CPA_COMMIT() asm volatile("cp.async.commit_group;" ::: "memory")
#define CPA_WAIT0()  asm volatile("cp.async.wait_group 0;" ::: "memory")

// split a float4 into bf16x2 hi/lo packed words
__device__ __forceinline__ void split4(float4 v, u32& h0, u32& h1, u32& l0, u32& l1) {
    asm("cvt.rn.bf16x2.f32 %0,%1,%2;" : "=r"(h0) : "f"(v.y), "f"(v.x));
    asm("cvt.rn.bf16x2.f32 %0,%1,%2;" : "=r"(h1) : "f"(v.w), "f"(v.z));
    float r0 = v.x - __int_as_float((int)(h0 << 16));
    float r1 = v.y - __int_as_float((int)(h0 & 0xFFFF0000u));
    float r2 = v.z - __int_as_float((int)(h1 << 16));
    float r3 = v.w - __int_as_float((int)(h1 & 0xFFFF0000u));
    asm("cvt.rn.bf16x2.f32 %0,%1,%2;" : "=r"(l0) : "f"(r1), "f"(r0));
    asm("cvt.rn.bf16x2.f32 %0,%1,%2;" : "=r"(l1) : "f"(r3), "f"(r2));
}
// pack 2 consecutive elems -> (hi bf16x2, lo bf16x2)
__device__ __forceinline__ uint2 pack2(float x, float y) {
    u32 h, lo;
    asm("cvt.rn.bf16x2.f32 %0,%1,%2;" : "=r"(h) : "f"(y), "f"(x));
    float rx = x - __int_as_float((int)(h << 16));
    float ry = y - __int_as_float((int)(h & 0xFFFF0000u));
    asm("cvt.rn.bf16x2.f32 %0,%1,%2;" : "=r"(lo) : "f"(ry), "f"(rx));
    return make_uint2(h, lo);
}

// ---------------- scratch ----------------
__device__ float g_q[(size_t)B * CDIM * NSP];                 // exp(q) fp32
__device__ __align__(16) uint2 g_kp[(size_t)B * CDIM * 2048]; // exp(k) (hi,lo) per 2 elems
__device__ __align__(16) uint2 g_vp[(size_t)B * CDIM * 2048]; // v (hi,lo) per 2 elems
__device__ float g_Sp[(size_t)B * HEADS * 4 * DH * DH];
__device__ float g_Zp64[(size_t)B * 64 * 2 * 128];            // [b][t][half][row]
__device__ float g_zs[B * 128];                               // reduced Z
__device__ __align__(16) unsigned short g_Wh[384 * 128];
__device__ __align__(16) unsigned short g_Wl[384 * 128];
__device__ __align__(16) unsigned short g_Mbh[(size_t)B * 16384];
__device__ __align__(16) unsigned short g_Mbl[(size_t)B * 16384];

// ---------------------------------------------------------------------------
// Kernel 0: split Wqkv into bf16 hi/lo
// ---------------------------------------------------------------------------
__global__ void k_splitW(const float* __restrict__ W) {
    for (int i = blockIdx.x * blockDim.x + threadIdx.x; i < 384 * 128;
         i += gridDim.x * blockDim.x) {
        float w = W[i];
        __nv_bfloat16 hb = __float2bfloat16(w);
        float hf = __bfloat162float(hb);
        __nv_bfloat16 lb = __float2bfloat16(w - hf);
        g_Wh[i] = __bfloat16_as_ushort(hb);
        g_Wl[i] = __bfloat16_as_ushort(lb);
    }
}

// ---------------------------------------------------------------------------
// Kernel 1: qkv = Wqkv @ x (split-bf16 mma.sync, 64-wide n tiles, 2 CTA/SM)
// FUSED epilogue: rb=0 -> exp(q) fp32; rb=1 -> exp(k) + Z partials + bf16
// pair-pack; rb=2 -> v bf16 pair-pack.   [R12 proven version]
// ---------------------------------------------------------------------------
#define SMEM_K1 104448
__global__ void __launch_bounds__(256) k_gemm_qkv(const float* __restrict__ x) {
    extern __shared__ char sm[];
    const u32 sbase = (u32)__cvta_generic_to_shared(sm);
    const u32 oBh = 0, oBl = 17408, oAh = 34816, oAl = 69632;
    float* stage = (float*)(sm + oAh);
    const int t = blockIdx.x, b = blockIdx.y;
    const int tid = threadIdx.x;
    const float* xb = x + (size_t)b * CDIM * NSP + t * 64;

#pragma unroll
    for (int it = 0; it < 8; it++) {
        int u = tid + it * 256;
        int k = u >> 4, nc = (u & 15) << 2;
        float4 v = *(const float4*)(xb + (size_t)k * NSP + nc);
        *(float4*)(stage + k * 68 + nc) = v;
    }
    __syncthreads();

#pragma unroll
    for (int it = 0; it < 4; it++) {
        int v = tid + it * 256;
        int n = v & 63, k8 = v >> 6;
        float f[8];
#pragma unroll
        for (int j = 0; j < 8; j++) f[j] = stage[(k8 * 8 + j) * 68 + n];
        u32 hw[4], lw[4];
#pragma unroll
        for (int jj = 0; jj < 2; jj++) {
            float4 q4 = make_float4(f[4 * jj], f[4 * jj + 1], f[4 * jj + 2], f[4 * jj + 3]);
            split4(q4, hw[2 * jj], hw[2 * jj + 1], lw[2 * jj], lw[2 * jj + 1]);
        }
        u32 off = n * 272 + k8 * 16;
        *(uint4*)(sm + oBh + off) = make_uint4(hw[0], hw[1], hw[2], hw[3]);
        *(uint4*)(sm + oBl + off) = make_uint4(lw[0], lw[1], lw[2], lw[3]);
    }
    __syncthreads();

    const int l = tid & 31, wid = tid >> 5;
    const int wm = (wid & 3) * 32;
    const int nh = (wid >> 2) * 32;
    const u32 aoff = (u32)((wm + (l & 15)) * 272 + (l >> 4) * 16);
    const u32 boff = (u32)((nh + (l & 7) + ((l >> 4) << 3)) * 272 + (((l >> 3) & 1) << 4));

    for (int rb = 0; rb < 3; rb++) {
        {
            const uint4* gh = (const uint4*)(g_Wh + (size_t)rb * 128 * 128);
            const uint4* gl = (const uint4*)(g_Wl + (size_t)rb * 128 * 128);
#pragma unroll
            for (int it = 0; it < 8; it++) {
                int u = tid + it * 256;
                int r = u >> 4, c = u & 15;
                u32 off = r * 272 + c * 16;
                *(uint4*)(sm + oAh + off) = gh[r * 16 + c];
                *(uint4*)(sm + oAl + off) = gl[r * 16 + c];
            }
        }
        __syncthreads();

        float acc[2][4][4];
#pragma unroll
        for (int mt = 0; mt < 2; mt++)
#pragma unroll
            for (int nt = 0; nt < 4; nt++)
#pragma unroll
                for (int q = 0; q < 4; q++) acc[mt][nt][q] = 0.f;

#pragma unroll
        for (int kc = 0; kc < 8; kc++) {
            u32 ah[2][4], al_[2][4], bhf[2][4], blf[2][4];
#pragma unroll
            for (int mt = 0; mt < 2; mt++) {
                u32 o = aoff + mt * (16 * 272) + kc * 32;
                ldm4(ah[mt],  sbase + oAh + o);
                ldm4(al_[mt], sbase + oAl + o);
            }
#pragma unroll
            for (int p = 0; p < 2; p++) {
                u32 o = boff + p * (16 * 272) + kc * 32;
                ldm4(bhf[p], sbase + oBh + o);
                ldm4(blf[p], sbase + oBl + o);
            }
#pragma unroll
            for (int mt = 0; mt < 2; mt++)
#pragma unroll
                for (int nt = 0; nt < 4; nt++) {
                    int p = nt >> 1, q = (nt & 1) * 2;
                    mma16816(acc[mt][nt], ah[mt],  bhf[p][q], bhf[p][q + 1]);
                    mma16816(acc[mt][nt], al_[mt], bhf[p][q], bhf[p][q + 1]);
                    mma16816(acc[mt][nt], ah[mt],  blf[p][q], blf[p][q + 1]);
                }
        }

        if (rb == 0) {
#pragma unroll
            for (int mt = 0; mt < 2; mt++)
#pragma unroll
                for (int rh = 0; rh < 2; rh++) {
                    int row = wm + mt * 16 + (l >> 2) + rh * 8;
                    float* outp = g_q + ((size_t)b * CDIM + row) * NSP + t * 64;
#pragma unroll
                    for (int nt = 0; nt < 4; nt++) {
                        bool up = (mt == 0) || (rh == 0 && nt < 2);
                        float2 o2;
                        o2.x = exp_sel(acc[mt][nt][rh * 2 + 0], up);
                        o2.y = exp_sel(acc[mt][nt][rh * 2 + 1], up);
                        *(float2*)(outp + nh + nt * 8 + (l & 3) * 2) = o2;
                    }
                }
        } else if (rb == 1) {
#pragma unroll
            for (int mt = 0; mt < 2; mt++)
#pragma unroll
                for (int rh = 0; rh < 2; rh++)
#pragma unroll
                    for (int nt = 0; nt < 4; nt++) {
                        bool up = (mt == 0) || (rh == 0 && nt < 2);
                        acc[mt][nt][rh * 2 + 0] = exp_sel(acc[mt][nt][rh * 2 + 0], up);
                        acc[mt][nt][rh * 2 + 1] = exp_sel(acc[mt][nt][rh * 2 + 1], up);
                    }
#pragma unroll
            for (int mt = 0; mt < 2; mt++)
#pragma unroll
                for (int rh = 0; rh < 2; rh++) {
                    int row = wm + mt * 16 + (l >> 2) + rh * 8;
                    float s = 0.f;
#pragma unroll
                    for (int nt = 0; nt < 4; nt++)
                        s += acc[mt][nt][rh * 2 + 0] + acc[mt][nt][rh * 2 + 1];
                    s += __shfl_xor_sync(0xffffffffu, s, 1);
                    s += __shfl_xor_sync(0xffffffffu, s, 2);
                    if ((l & 3) == 0)
                        g_Zp64[((size_t)b * 64 + t) * 256 + (wid >> 2) * 128 + row] = s;
                }
#pragma unroll
            for (int mt = 0; mt < 2; mt++)
#pragma unroll
                for (int rh = 0; rh < 2; rh++) {
                    int row = wm + mt * 16 + (l >> 2) + rh * 8;
                    uint2* kr = g_kp + ((size_t)b * CDIM + row) * 2048 + t * 32 + (nh >> 1);
#pragma unroll
                    for (int nt = 0; nt < 4; nt++)
                        kr[nt * 4 + (l & 3)] =
                            pack2(acc[mt][nt][rh * 2 + 0], acc[mt][nt][rh * 2 + 1]);
                }
        } else {
#pragma unroll
            for (int mt = 0; mt < 2; mt++)
#pragma unroll
                for (int rh = 0; rh < 2; rh++) {
                    int row = wm + mt * 16 + (l >> 2) + rh * 8;
                    uint2* vr = g_vp + ((size_t)b * CDIM + row) * 2048 + t * 32 + (nh >> 1);
#pragma unroll
                    for (int nt = 0; nt < 4; nt++)
                        vr[nt * 4 + (l & 3)] =
                            pack2(acc[mt][nt][rh * 2 + 0], acc[mt][nt][rh * 2 + 1]);
                }
        }
        __syncthreads();
    }
}

// ---------------------------------------------------------------------------
// Kernel 1b: reduce Z partials once per batch -> g_zs[b][128]
// ---------------------------------------------------------------------------
__global__ void __launch_bounds__(256) k_z() {
    __shared__ float zpart[256];
    const int b = blockIdx.x;
    const int tid = threadIdx.x;
    const float* zp = g_Zp64 + (size_t)b * 16384 + (tid >> 7) * 128 + (tid & 127);
    float z = 0.f;
#pragma unroll 8
    for (int s = 0; s < 64; s++) z += zp[(size_t)s * 256];
    zpart[tid] = z;
    __syncthreads();
    if (tid < 128) g_zs[b * 128 + tid] = zpart[tid] + zpart[tid + 128];
}

// ---------------------------------------------------------------------------
// Kernel 2: Sp[d][e] = sum_n exp(k[d,n])*v[e,n] via split-bf16 mma.
// Register double-buffered.  grid = (4 heads, 4 slabs of 1024 n, 32 batches)
// ---------------------------------------------------------------------------
__global__ void __launch_bounds__(256) k_reduce_kv() {
    __shared__ __align__(16) char sm2[34816 + 4224];
    const u32 sbase = (u32)__cvta_generic_to_shared(sm2);
    const u32 oAh = 0, oAl = 8704, oBh = 17408, oBl = 26112;
    float* sbuf = (float*)(sm2 + 34816);
    const int h = blockIdx.x, p = blockIdx.y, b = blockIdx.z;
    const int tid = threadIdx.x;
    const int l = tid & 31, w = tid >> 5;

    const int mt = w & 1, np = (w >> 1) & 1, kh = w >> 2;
    const u32 aoff = (u32)((mt * 16 + (l & 15)) * 272 + (l >> 4) * 16);
    const u32 boff = (u32)((np * 16 + (l & 7) + ((l >> 4) << 3)) * 272 + (((l >> 3) & 1) << 4));

    const uint4* kbase[4];
    const uint4* vbase[4];
#pragma unroll
    for (int i = 0; i < 4; i++) {
        kbase[i] = (const uint4*)(g_kp + ((size_t)b * CDIM + h * 32 + w + i * 8) * 2048)
                   + p * 256 + l;
        vbase[i] = (const uint4*)(g_vp + ((size_t)b * CDIM + h * 32 + w + i * 8) * 2048)
                   + p * 256 + l;
    }

    float acc[2][4];
#pragma unroll
    for (int g = 0; g < 2; g++)
#pragma unroll
        for (int q = 0; q < 4; q++) acc[g][q] = 0.f;

    uint4 kreg[4], vreg[4];
#pragma unroll
    for (int i = 0; i < 4; i++) { kreg[i] = kbase[i][0]; vreg[i] = vbase[i][0]; }

    for (int ch = 0; ch < 8; ch++) {
        __syncthreads();
#pragma unroll
        for (int i = 0; i < 4; i++) {
            int d = w + i * 8;
            *(uint2*)(sm2 + oAh + d * 272 + l * 8) = make_uint2(kreg[i].x, kreg[i].z);
            *(uint2*)(sm2 + oAl + d * 272 + l * 8) = make_uint2(kreg[i].y, kreg[i].w);
            *(uint2*)(sm2 + oBh + d * 272 + l * 8) = make_uint2(vreg[i].x, vreg[i].z);
            *(uint2*)(sm2 + oBl + d * 272 + l * 8) = make_uint2(vreg[i].y, vreg[i].w);
        }
        __syncthreads();
        if (ch < 7) {
#pragma unroll
            for (int i = 0; i < 4; i++) {
                kreg[i] = kbase[i][(ch + 1) * 32];
                vreg[i] = vbase[i][(ch + 1) * 32];
            }
        }
#pragma unroll
        for (int kc2 = 0; kc2 < 4; kc2++) {
            int kc = kh * 4 + kc2;
            u32 ah[4], al_[4], bh_[4], bl_[4];
            ldm4(ah,  sbase + oAh + aoff + kc * 32);
            ldm4(al_, sbase + oAl + aoff + kc * 32);
            ldm4(bh_, sbase + oBh + boff + kc * 32);
            ldm4(bl_, sbase + oBl + boff + kc * 32);
#pragma unroll
            for (int g = 0; g < 2; g++) {
                mma16816(acc[g], ah,  bh_[g * 2], bh_[g * 2 + 1]);
                mma16816(acc[g], al_, bh_[g * 2], bh_[g * 2 + 1]);
                mma16816(acc[g], ah,  bl_[g * 2], bl_[g * 2 + 1]);
            }
        }
    }

    __syncthreads();
    if (kh == 0) {
#pragma unroll
        for (int g = 0; g < 2; g++)
#pragma unroll
            for (int rh = 0; rh < 2; rh++)
#pragma unroll
                for (int q = 0; q < 2; q++) {
                    int row = mt * 16 + (l >> 2) + rh * 8;
                    int col = np * 16 + g * 8 + (l & 3) * 2 + q;
                    sbuf[row * 33 + col] = acc[g][rh * 2 + q];
                }
    }
    __syncthreads();
    if (kh == 1) {
#pragma unroll
        for (int g = 0; g < 2; g++)
#pragma unroll
            for (int rh = 0; rh < 2; rh++)
#pragma unroll
                for (int q = 0; q < 2; q++) {
                    int row = mt * 16 + (l >> 2) + rh * 8;
                    int col = np * 16 + g * 8 + (l & 3) * 2 + q;
                    sbuf[row * 33 + col] += acc[g][rh * 2 + q];
                }
    }
    __syncthreads();
    float* Sp = g_Sp + (((size_t)(b * HEADS + h) * 4 + p) << 10);
#pragma unroll
    for (int i2 = 0; i2 < 4; i2++) {
        int idx = tid + i2 * 256;
        Sp[idx] = sbuf[(idx >> 5) * 33 + (idx & 31)];
    }
}

// ---------------------------------------------------------------------------
// Kernel 3: ctx = (sum_p Sp)/Z (Z precomputed by k_z); M_b = Wout∘ctx bf16
// hi/lo.  grid = (32 batches, 8 o-slices)
// ---------------------------------------------------------------------------
__global__ void __launch_bounds__(256) k_ctx_M(const float* __restrict__ Wout) {
    __shared__ float ctxs[4 * 32 * 33];
    __shared__ float zs[128];
    const int b = blockIdx.x;
    const int og = blockIdx.y;
    const int tid = threadIdx.x;
    if (tid < 128) zs[tid] = g_zs[b * 128 + tid];
    __syncthreads();
#pragma unroll
    for (int s2 = 0; s2 < 16; s2++) {
        int idx = tid + s2 * 256;
        int h = idx >> 10, d = (idx >> 5) & 31, e = idx & 31;
        float s = 0.f;
#pragma unroll
        for (int p = 0; p < 4; p++)
            s += g_Sp[(((size_t)(b * HEADS + h) * 4 + p) << 10) + (idx & 1023)];
        ctxs[h * 1056 + d * 33 + e] = s / zs[h * 32 + d];
    }
    __syncthreads();
    unsigned short* Mh = g_Mbh + (size_t)b * 16384;
    unsigned short* Ml = g_Mbl + (size_t)b * 16384;
#pragma unroll
    for (int s8 = 0; s8 < 8; s8++) {
        int pidx = og * 2048 + tid + s8 * 256;
        int o = pidx >> 7, hd = pidx & 127;
        int h = hd >> 5, dd = hd & 31;
        const float* wrow = Wout + o * 128 + h * 32;
        const float* crow = ctxs + h * 1056 + dd * 33;
        float s = 0.f;
#pragma unroll
        for (int e = 0; e < 32; e++) s += __ldg(wrow + e) * crow[e];
        __nv_bfloat16 hb = __float2bfloat16(s);
        float hf = __bfloat162float(hb);
        Mh[pidx] = __bfloat16_as_ushort(hb);
        Ml[pidx] = __bfloat16_as_ushort(__float2bfloat16(s - hf));
    }
}

// ---------------------------------------------------------------------------
// Kernel 4: out = LayerNorm( M_b @ softmax_d(q) + bout ); q pre-exp'd.
// M_b tiles prefetched via cp.async.  grid = (64 n-tiles, 32 batches)
// ---------------------------------------------------------------------------
#define SMEM_K4 107008
__global__ void __launch_bounds__(256) k_out(const float* __restrict__ bout,
                                             const float* __restrict__ lnw,
                                             const float* __restrict__ lnb,
                                             float* __restrict__ out) {
    extern __shared__ char sm[];
    const u32 sbase = (u32)__cvta_generic_to_shared(sm);
    const u32 oBh = 0, oBl = 17408, oAh = 34816, oAl = 69632;
    float* stage = (float*)(sm + oAh);
    float* ssum  = (float*)(sm + 104448);
    float* red   = (float*)(sm + 105472);
    float* meanv = (float*)(sm + 106496);
    float* rstd  = (float*)(sm + 106752);
    const int t = blockIdx.x, b = blockIdx.y;
    const int tid = threadIdx.x;
    const float* qb = g_q + (size_t)b * CDIM * NSP + t * 64;

    {
        const uint4* gl = (const uint4*)(g_Mbl + (size_t)b * 16384);
#pragma unroll
        for (int it = 0; it < 8; it++) {
            int u = tid + it * 256;
            int r = u >> 4, c = u & 15;
            CPA16(sbase + oAl + r * 272 + c * 16, gl + u);
        }
        CPA_COMMIT();
    }

#pragma unroll
    for (int it = 0; it < 8; it++) {
        int u = tid + it * 256;
        int k = u >> 4, nc = (u & 15) << 2;
        float4 v = *(const float4*)(qb + (size_t)k * NSP + nc);
        *(float4*)(stage + k * 68 + nc) = v;
    }
    __syncthreads();

    {
        int n = tid & 63, hh = tid >> 6;
        float s = 0.f;
#pragma unroll
        for (int kk = 0; kk < 32; kk++) s += stage[(hh * 32 + kk) * 68 + n];
        ssum[hh * 64 + n] = 1.f / s;
    }
    __syncthreads();

#pragma unroll
    for (int it = 0; it < 4; it++) {
        int v = tid + it * 256;
        int n = v & 63, k8 = v >> 6;
        float rn_ = ssum[(k8 >> 2) * 64 + n];
        u32 hw[4], lw[4];
#pragma unroll
        for (int jj = 0; jj < 2; jj++) {
            float4 q4;
            q4.x = stage[(k8 * 8 + 4 * jj + 0) * 68 + n] * rn_;
            q4.y = stage[(k8 * 8 + 4 * jj + 1) * 68 + n] * rn_;
            q4.z = stage[(k8 * 8 + 4 * jj + 2) * 68 + n] * rn_;
            q4.w = stage[(k8 * 8 + 4 * jj + 3) * 68 + n] * rn_;
            split4(q4, hw[2 * jj], hw[2 * jj + 1], lw[2 * jj], lw[2 * jj + 1]);
        }
        u32 off = n * 272 + k8 * 16;
        *(uint4*)(sm + oBh + off) = make_uint4(hw[0], hw[1], hw[2], hw[3]);
        *(uint4*)(sm + oBl + off) = make_uint4(lw[0], lw[1], lw[2], lw[3]);
    }
    __syncthreads();

    {
        const uint4* gh = (const uint4*)(g_Mbh + (size_t)b * 16384);
#pragma unroll
        for (int it = 0; it < 8; it++) {
            int u = tid + it * 256;
            int r = u >> 4, c = u & 15;
            CPA16(sbase + oAh + r * 272 + c * 16, gh + u);
        }
        CPA_COMMIT();
        CPA_WAIT0();
    }
    __syncthreads();

    const int l = tid & 31, wid = tid >> 5;
    const int wm = (wid & 3) * 32;
    const int nh = (wid >> 2) * 32;
    const u32 aoff = (u32)((wm + (l & 15)) * 272 + (l >> 4) * 16);
    const u32 boff = (u32)((nh + (l & 7) + ((l >> 4) << 3)) * 272 + (((l >> 3) & 1) << 4));

    float acc[2][4][4];
#pragma unroll
    for (int mt = 0; mt < 2; mt++)
#pragma unroll
        for (int nt = 0; nt < 4; nt++)
#pragma unroll
            for (int q = 0; q < 4; q++) acc[mt][nt][q] = 0.f;

#pragma unroll
    for (int kc = 0; kc < 8; kc++) {
        u32 ah[2][4], al_[2][4], bhf[2][4], blf[2][4];
#pragma unroll
        for (int mt = 0; mt < 2; mt++) {
            u32 o = aoff + mt * (16 * 272) + kc * 32;
            ldm4(ah[mt],  sbase + oAh + o);
            ldm4(al_[mt], sbase + oAl + o);
        }
#pragma unroll
        for (int p = 0; p < 2; p++) {
            u32 o = boff + p * (16 * 272) + kc * 32;
            ldm4(bhf[p], sbase + oBh + o);
            ldm4(blf[p], sbase + oBl + o);
        }
#pragma unroll
        for (int mt = 0; mt < 2; mt++)
#pragma unroll
            for (int nt = 0; nt < 4; nt++) {
                int p = nt >> 1, q = (nt & 1) * 2;
                mma16816(acc[mt][nt], ah[mt],  bhf[p][q], bhf[p][q + 1]);
                mma16816(acc[mt][nt], al_[mt], bhf[p][q], bhf[p][q + 1]);
                mma16816(acc[mt][nt], ah[mt],  blf[p][q], blf[p][q + 1]);
            }
    }

#pragma unroll
    for (int mt = 0; mt < 2; mt++)
#pragma unroll
        for (int rh = 0; rh < 2; rh++) {
            float bo = __ldg(bout + wm + mt * 16 + (l >> 2) + rh * 8);
#pragma unroll
            for (int nt = 0; nt < 4; nt++) {
                acc[mt][nt][rh * 2 + 0] += bo;
                acc[mt][nt][rh * 2 + 1] += bo;
            }
        }

#pragma unroll
    for (int q = 0; q < 2; q++) {
#pragma unroll
        for (int nt = 0; nt < 4; nt++) {
            float cs = acc[0][nt][q] + acc[0][nt][2 + q] + acc[1][nt][q] + acc[1][nt][2 + q];
            cs += __shfl_xor_sync(0xffffffffu, cs, 4);
            cs += __shfl_xor_sync(0xffffffffu, cs, 8);
            cs += __shfl_xor_sync(0xffffffffu, cs, 16);
            if (l < 4) red[(wid & 3) * 64 + nh + nt * 8 + l * 2 + q] = cs;
        }
    }
    __syncthreads();
    if (tid < 64) {
        float s = red[tid] + red[64 + tid] + red[128 + tid] + red[192 + tid];
        meanv[tid] = s * (1.f / 128.f);
    }
    __syncthreads();
#pragma unroll
    for (int q = 0; q < 2; q++) {
#pragma unroll
        for (int nt = 0; nt < 4; nt++) {
            float cm = meanv[nh + nt * 8 + (l & 3) * 2 + q];
            float d0 = acc[0][nt][q] - cm, d1 = acc[0][nt][2 + q] - cm;
            float d2 = acc[1][nt][q] - cm, d3 = acc[1][nt][2 + q] - cm;
            float cs = d0 * d0 + d1 * d1 + d2 * d2 + d3 * d3;
            cs += __shfl_xor_sync(0xffffffffu, cs, 4);
            cs += __shfl_xor_sync(0xffffffffu, cs, 8);
            cs += __shfl_xor_sync(0xffffffffu, cs, 16);
            if (l < 4) red[(wid & 3) * 64 + nh + nt * 8 + l * 2 + q] = cs;
        }
    }
    __syncthreads();
    if (tid < 64) {
        float s = red[tid] + red[64 + tid] + red[128 + tid] + red[192 + tid];
        rstd[tid] = rsqrtf(s * (1.f / 128.f) + EPS);
    }
    __syncthreads();

#pragma unroll
    for (int mt = 0; mt < 2; mt++)
#pragma unroll
        for (int rh = 0; rh < 2; rh++) {
            int row = wm + mt * 16 + (l >> 2) + rh * 8;
            float lw = __ldg(lnw + row);
            float lb = __ldg(lnb + row);
#pragma unroll
            for (int nt = 0; nt < 4; nt++) {
                int col = nh + nt * 8 + (l & 3) * 2;
                float m0 = meanv[col], m1 = meanv[col + 1];
                float r0 = rstd[col], r1 = rstd[col + 1];
                float2 o2;
                o2.x = (acc[mt][nt][rh * 2 + 0] - m0) * r0 * lw + lb;
                o2.y = (acc[mt][nt][rh * 2 + 1] - m1) * r1 * lw + lb;
                *(float2*)(out + ((size_t)b * CDIM + row) * NSP + t * 64 + col) = o2;
            }
        }
}

// ---------------------------------------------------------------------------
extern "C" void kernel_launch(void* const* d_in, const int* in_sizes, int n_in,
                              void* d_out, int out_size) {
    const float* x    = (const float*)d_in[0];
    const float* Wqkv = (const float*)d_in[1];
    const float* Wout = (const float*)d_in[2];
    const float* bout = (const float*)d_in[3];
    const float* lnw  = (const float*)d_in[4];
    const float* lnb  = (const float*)d_in[5];
    float* out = (float*)d_out;

    cudaFuncSetAttribute(k_gemm_qkv, cudaFuncAttributeMaxDynamicSharedMemorySize, SMEM_K1);
    cudaFuncSetAttribute(k_out, cudaFuncAttributeMaxDynamicSharedMemorySize, SMEM_K4);

    k_splitW<<<48, 256>>>(Wqkv);
    k_gemm_qkv<<<dim3(64, B), 256, SMEM_K1>>>(x);
    k_z<<<B, 256>>>();
    k_reduce_kv<<<dim3(HEADS, 4, B), 256>>>();
    k_ctx_M<<<dim3(B, 8), 256>>>(Wout);
    k_out<<<dim3(64, B), 256, SMEM_K4>>>(bout, lnw, lnb, out);
}

// round 17
// speedup vs baseline: 1.5530x; 1.0224x over previous
#include <cuda_runtime.h>
#include <cuda_bf16.h>
#include <math.h>

#define B    32
#define CDIM 128
#define NSP  4096
#define HEADS 4
#define DH   32
#define EPS  1e-5f

typedef unsigned long long u64;
typedef unsigned int u32;

// ---------------- FFMA-only exp ----------------
__device__ __forceinline__ float exp_poly(float x) {
    float y = x * 1.4426950408889634f;
    float z = y + 12582912.0f;
    int   zb = __float_as_int(z);
    float n = z - 12582912.0f;
    float f = y - n;
    float p = 0.0096180f;
    p = fmaf(p, f, 0.0555041f);
    p = fmaf(p, f, 0.2402265f);
    p = fmaf(p, f, 0.6931472f);
    p = fmaf(p, f, 1.0f);
    return __int_as_float(__float_as_int(p) + (zb << 23));
}
__device__ __forceinline__ float exp_sel(float x, bool poly) {
    return poly ? exp_poly(x) : __expf(x);
}

// ---------------- mma.sync / ldmatrix wrappers ----------------
__device__ __forceinline__ void ldm4(u32* d, u32 addr) {
    asm volatile("ldmatrix.sync.aligned.m8n8.x4.shared.b16 {%0,%1,%2,%3},[%4];"
                 : "=r"(d[0]), "=r"(d[1]), "=r"(d[2]), "=r"(d[3]) : "r"(addr));
}
__device__ __forceinline__ void mma16816(float* c, const u32* a, u32 b0, u32 b1) {
    asm volatile("mma.sync.aligned.m16n8k16.row.col.f32.bf16.bf16.f32 "
                 "{%0,%1,%2,%3},{%4,%5,%6,%7},{%8,%9},{%0,%1,%2,%3};"
                 : "+f"(c[0]), "+f"(c[1]), "+f"(c[2]), "+f"(c[3])
                 : "r"(a[0]), "r"(a[1]), "r"(a[2]), "r"(a[3]), "r"(b0), "r"(b1));
}

// cp.async helpers
#define CPA16(saddr, gptr) \
    asm volatile("cp.async.cg.shared.global [%0],[%1],16;" :: "r"(saddr), "l"(gptr) : "memory")
#define CPA_COMMIT() asm volatile("cp.async.commit_group;" ::: "memory")
#define CPA_WAIT0()  asm volatile("cp.async.wait_group 0;" ::: "memory")

// split a float4 into bf16x2 hi/lo packed words
__device__ __forceinline__ void split4(float4 v, u32& h0, u32& h1, u32& l0, u32& l1) {
    asm("cvt.rn.bf16x2.f32 %0,%1,%2;" : "=r"(h0) : "f"(v.y), "f"(v.x));
    asm("cvt.rn.bf16x2.f32 %0,%1,%2;" : "=r"(h1) : "f"(v.w), "f"(v.z));
    float r0 = v.x - __int_as_float((int)(h0 << 16));
    float r1 = v.y - __int_as_float((int)(h0 & 0xFFFF0000u));
    float r2 = v.z - __int_as_float((int)(h1 << 16));
    float r3 = v.w - __int_as_float((int)(h1 & 0xFFFF0000u));
    asm("cvt.rn.bf16x2.f32 %0,%1,%2;" : "=r"(l0) : "f"(r1), "f"(r0));
    asm("cvt.rn.bf16x2.f32 %0,%1,%2;" : "=r"(l1) : "f"(r3), "f"(r2));
}
// pack 2 consecutive elems -> (hi bf16x2, lo bf16x2)
__device__ __forceinline__ uint2 pack2(float x, float y) {
    u32 h, lo;
    asm("cvt.rn.bf16x2.f32 %0,%1,%2;" : "=r"(h) : "f"(y), "f"(x));
    float rx = x - __int_as_float((int)(h << 16));
    float ry = y - __int_as_float((int)(h & 0xFFFF0000u));
    asm("cvt.rn.bf16x2.f32 %0,%1,%2;" : "=r"(lo) : "f"(ry), "f"(rx));
    return make_uint2(h, lo);
}

// ---------------- scratch ----------------
__device__ float g_q[(size_t)B * CDIM * NSP];        // exp(q) fp32
__device__ float g_Spt[(size_t)B * 64 * 4096];       // per-tile context partials
__device__ float g_Zp64[(size_t)B * 64 * 2 * 128];   // [b][t][half][row]
__device__ float g_zs[B * 128];                      // reduced Z
__device__ float g_ctx[(size_t)B * 4096];            // ctx = S/Z
__device__ __align__(16) unsigned short g_Wh[384 * 128];
__device__ __align__(16) unsigned short g_Wl[384 * 128];
__device__ __align__(16) unsigned short g_Mbh[(size_t)B * 16384];
__device__ __align__(16) unsigned short g_Mbl[(size_t)B * 16384];

// ---------------------------------------------------------------------------
// Kernel 0: split Wqkv into bf16 hi/lo
// ---------------------------------------------------------------------------
__global__ void k_splitW(const float* __restrict__ W) {
    for (int i = blockIdx.x * blockDim.x + threadIdx.x; i < 384 * 128;
         i += gridDim.x * blockDim.x) {
        float w = W[i];
        __nv_bfloat16 hb = __float2bfloat16(w);
        float hf = __bfloat162float(hb);
        __nv_bfloat16 lb = __float2bfloat16(w - hf);
        g_Wh[i] = __bfloat16_as_ushort(hb);
        g_Wl[i] = __bfloat16_as_ushort(lb);
    }
}

// ---------------------------------------------------------------------------
// Kernel 1 (FUSED): qkv GEMM + exp + Z + IN-SMEM context reduction.
// rb=0 -> exp(q) fp32 to global; rb=1 -> exp(k) + Z partials + bf16 hi/lo to
// SMEM K; rb=2 -> v bf16 hi/lo to SMEM V. Then per-warp (head, e-half)
// context mma over this tile's 64 n: Sp partial -> g_Spt[b][t][h][32x32].
// grid = (64 n-tiles, 32 batches), 256 threads. 1 CTA/SM (174KB smem).
// ---------------------------------------------------------------------------
#define SMEM_K1 178176
__global__ void __launch_bounds__(256) k_gemm_qkv(const float* __restrict__ x) {
    extern __shared__ char sm[];
    const u32 sbase = (u32)__cvta_generic_to_shared(sm);
    const u32 oBh = 0, oBl = 17408, oAh = 34816, oAl = 69632;
    const u32 oKh = 104448, oKl = 122880, oVh = 141312, oVl = 159744;
    float* stage = (float*)(sm + oAh);
    const int t = blockIdx.x, b = blockIdx.y;
    const int tid = threadIdx.x;
    const float* xb = x + (size_t)b * CDIM * NSP + t * 64;

    // phase 1: x tile [128k][64n] -> fp32 stage stride 68
#pragma unroll
    for (int it = 0; it < 8; it++) {
        int u = tid + it * 256;
        int k = u >> 4, nc = (u & 15) << 2;
        float4 v = *(const float4*)(xb + (size_t)k * NSP + nc);
        *(float4*)(stage + k * 68 + nc) = v;
    }
    __syncthreads();

    // phase 2: transpose-convert to bf16 hi/lo [n][k] layout
#pragma unroll
    for (int it = 0; it < 4; it++) {
        int v = tid + it * 256;
        int n = v & 63, k8 = v >> 6;
        float f[8];
#pragma unroll
        for (int j = 0; j < 8; j++) f[j] = stage[(k8 * 8 + j) * 68 + n];
        u32 hw[4], lw[4];
#pragma unroll
        for (int jj = 0; jj < 2; jj++) {
            float4 q4 = make_float4(f[4 * jj], f[4 * jj + 1], f[4 * jj + 2], f[4 * jj + 3]);
            split4(q4, hw[2 * jj], hw[2 * jj + 1], lw[2 * jj], lw[2 * jj + 1]);
        }
        u32 off = n * 272 + k8 * 16;
        *(uint4*)(sm + oBh + off) = make_uint4(hw[0], hw[1], hw[2], hw[3]);
        *(uint4*)(sm + oBl + off) = make_uint4(lw[0], lw[1], lw[2], lw[3]);
    }
    __syncthreads();

    const int l = tid & 31, wid = tid >> 5;
    const int wm = (wid & 3) * 32;
    const int nh = (wid >> 2) * 32;
    const u32 aoff = (u32)((wm + (l & 15)) * 272 + (l >> 4) * 16);
    const u32 boff = (u32)((nh + (l & 7) + ((l >> 4) << 3)) * 272 + (((l >> 3) & 1) << 4));

    for (int rb = 0; rb < 3; rb++) {
        {
            const uint4* gh = (const uint4*)(g_Wh + (size_t)rb * 128 * 128);
            const uint4* gl = (const uint4*)(g_Wl + (size_t)rb * 128 * 128);
#pragma unroll
            for (int it = 0; it < 8; it++) {
                int u = tid + it * 256;
                int r = u >> 4, c = u & 15;
                u32 off = r * 272 + c * 16;
                *(uint4*)(sm + oAh + off) = gh[r * 16 + c];
                *(uint4*)(sm + oAl + off) = gl[r * 16 + c];
            }
        }
        __syncthreads();

        float acc[2][4][4];
#pragma unroll
        for (int mt = 0; mt < 2; mt++)
#pragma unroll
            for (int nt = 0; nt < 4; nt++)
#pragma unroll
                for (int q = 0; q < 4; q++) acc[mt][nt][q] = 0.f;

#pragma unroll
        for (int kc = 0; kc < 8; kc++) {
            u32 ah[2][4], al_[2][4], bhf[2][4], blf[2][4];
#pragma unroll
            for (int mt = 0; mt < 2; mt++) {
                u32 o = aoff + mt * (16 * 272) + kc * 32;
                ldm4(ah[mt],  sbase + oAh + o);
                ldm4(al_[mt], sbase + oAl + o);
            }
#pragma unroll
            for (int p = 0; p < 2; p++) {
                u32 o = boff + p * (16 * 272) + kc * 32;
                ldm4(bhf[p], sbase + oBh + o);
                ldm4(blf[p], sbase + oBl + o);
            }
#pragma unroll
            for (int mt = 0; mt < 2; mt++)
#pragma unroll
                for (int nt = 0; nt < 4; nt++) {
                    int p = nt >> 1, q = (nt & 1) * 2;
                    mma16816(acc[mt][nt], ah[mt],  bhf[p][q], bhf[p][q + 1]);
                    mma16816(acc[mt][nt], al_[mt], bhf[p][q], bhf[p][q + 1]);
                    mma16816(acc[mt][nt], ah[mt],  blf[p][q], blf[p][q + 1]);
                }
        }

        if (rb == 0) {
            // q: exp (hybrid p=10/16), store fp32 to global
#pragma unroll
            for (int mt = 0; mt < 2; mt++)
#pragma unroll
                for (int rh = 0; rh < 2; rh++) {
                    int row = wm + mt * 16 + (l >> 2) + rh * 8;
                    float* outp = g_q + ((size_t)b * CDIM + row) * NSP + t * 64;
#pragma unroll
                    for (int nt = 0; nt < 4; nt++) {
                        bool up = (mt == 0) || (rh == 0 && nt < 2);
                        float2 o2;
                        o2.x = exp_sel(acc[mt][nt][rh * 2 + 0], up);
                        o2.y = exp_sel(acc[mt][nt][rh * 2 + 1], up);
                        *(float2*)(outp + nh + nt * 8 + (l & 3) * 2) = o2;
                    }
                }
        } else if (rb == 1) {
            // k: exp, Z partials, pack to SMEM K
#pragma unroll
            for (int mt = 0; mt < 2; mt++)
#pragma unroll
                for (int rh = 0; rh < 2; rh++)
#pragma unroll
                    for (int nt = 0; nt < 4; nt++) {
                        bool up = (mt == 0) || (rh == 0 && nt < 2);
                        acc[mt][nt][rh * 2 + 0] = exp_sel(acc[mt][nt][rh * 2 + 0], up);
                        acc[mt][nt][rh * 2 + 1] = exp_sel(acc[mt][nt][rh * 2 + 1], up);
                    }
#pragma unroll
            for (int mt = 0; mt < 2; mt++)
#pragma unroll
                for (int rh = 0; rh < 2; rh++) {
                    int row = wm + mt * 16 + (l >> 2) + rh * 8;
                    float s = 0.f;
#pragma unroll
                    for (int nt = 0; nt < 4; nt++)
                        s += acc[mt][nt][rh * 2 + 0] + acc[mt][nt][rh * 2 + 1];
                    s += __shfl_xor_sync(0xffffffffu, s, 1);
                    s += __shfl_xor_sync(0xffffffffu, s, 2);
                    if ((l & 3) == 0)
                        g_Zp64[((size_t)b * 64 + t) * 256 + (wid >> 2) * 128 + row] = s;
                }
#pragma unroll
            for (int mt = 0; mt < 2; mt++)
#pragma unroll
                for (int rh = 0; rh < 2; rh++) {
                    int row = wm + mt * 16 + (l >> 2) + rh * 8;
#pragma unroll
                    for (int nt = 0; nt < 4; nt++) {
                        int col = nh + nt * 8 + (l & 3) * 2;
                        uint2 pr = pack2(acc[mt][nt][rh * 2 + 0], acc[mt][nt][rh * 2 + 1]);
                        *(u32*)(sm + oKh + row * 144 + col * 2) = pr.x;
                        *(u32*)(sm + oKl + row * 144 + col * 2) = pr.y;
                    }
                }
        } else {
            // v: pack to SMEM V
#pragma unroll
            for (int mt = 0; mt < 2; mt++)
#pragma unroll
                for (int rh = 0; rh < 2; rh++) {
                    int row = wm + mt * 16 + (l >> 2) + rh * 8;
#pragma unroll
                    for (int nt = 0; nt < 4; nt++) {
                        int col = nh + nt * 8 + (l & 3) * 2;
                        uint2 pr = pack2(acc[mt][nt][rh * 2 + 0], acc[mt][nt][rh * 2 + 1]);
                        *(u32*)(sm + oVh + row * 144 + col * 2) = pr.x;
                        *(u32*)(sm + oVl + row * 144 + col * 2) = pr.y;
                    }
                }
        }
        __syncthreads();
    }

    // ---- fused context mma: Sp[h][d][e] += sum_{n in tile} exp(k)[d,n]*v[e,n]
    // warp = (head hh = wid&3, e-half eh = wid>>2). Output 32d x 16e per warp.
    {
        const int hh = wid & 3, eh = wid >> 2;
        const u32 ka_off = (u32)((hh * 32 + (l & 15)) * 144 + (l >> 4) * 16);
        const u32 vb_off = (u32)((hh * 32 + eh * 16 + (l & 7) + ((l >> 4) << 3)) * 144
                                 + (((l >> 3) & 1) << 4));
        float sacc[2][2][4];
#pragma unroll
        for (int mt = 0; mt < 2; mt++)
#pragma unroll
            for (int nt = 0; nt < 2; nt++)
#pragma unroll
                for (int q = 0; q < 4; q++) sacc[mt][nt][q] = 0.f;

#pragma unroll
        for (int kc = 0; kc < 4; kc++) {
            u32 akh[2][4], akl[2][4], bvh[4], bvl[4];
#pragma unroll
            for (int mt = 0; mt < 2; mt++) {
                u32 o = ka_off + mt * (16 * 144) + kc * 32;
                ldm4(akh[mt], sbase + oKh + o);
                ldm4(akl[mt], sbase + oKl + o);
            }
            ldm4(bvh, sbase + oVh + vb_off + kc * 32);
            ldm4(bvl, sbase + oVl + vb_off + kc * 32);
#pragma unroll
            for (int mt = 0; mt < 2; mt++)
#pragma unroll
                for (int nt = 0; nt < 2; nt++) {
                    int q2 = nt * 2;
                    mma16816(sacc[mt][nt], akh[mt], bvh[q2], bvh[q2 + 1]);
                    mma16816(sacc[mt][nt], akl[mt], bvh[q2], bvh[q2 + 1]);
                    mma16816(sacc[mt][nt], akh[mt], bvl[q2], bvl[q2 + 1]);
                }
        }

        float* sp = g_Spt + ((size_t)(b * 64 + t) * 4 + hh) * 1024;
#pragma unroll
        for (int mt = 0; mt < 2; mt++)
#pragma unroll
            for (int rh = 0; rh < 2; rh++) {
                int d = mt * 16 + (l >> 2) + rh * 8;
#pragma unroll
                for (int nt = 0; nt < 2; nt++) {
                    int e0 = eh * 16 + nt * 8 + (l & 3) * 2;
                    *(float2*)(sp + d * 32 + e0) =
                        make_float2(sacc[mt][nt][rh * 2], sacc[mt][nt][rh * 2 + 1]);
                }
            }
    }
}

// ---------------------------------------------------------------------------
// Kernel 1b: reduce Z partials once per batch -> g_zs[b][128]
// ---------------------------------------------------------------------------
__global__ void __launch_bounds__(256) k_z() {
    __shared__ float zpart[256];
    const int b = blockIdx.x;
    const int tid = threadIdx.x;
    const float* zp = g_Zp64 + (size_t)b * 16384 + (tid >> 7) * 128 + (tid & 127);
    float z = 0.f;
#pragma unroll 8
    for (int s = 0; s < 64; s++) z += zp[(size_t)s * 256];
    zpart[tid] = z;
    __syncthreads();
    if (tid < 128) g_zs[b * 128 + tid] = zpart[tid] + zpart[tid + 128];
}

// ---------------------------------------------------------------------------
// Kernel 2: ctx[b][idx] = (sum_t Spt[b][t][idx]) / Z.  grid = (32, 8).
// ---------------------------------------------------------------------------
__global__ void __launch_bounds__(256) k_ctx() {
    const int b = blockIdx.x, og = blockIdx.y;
    const int tid = threadIdx.x;
#pragma unroll
    for (int s2 = 0; s2 < 2; s2++) {
        int idx = og * 512 + tid + s2 * 256;
        const float* sp = g_Spt + (size_t)b * 262144 + idx;
        float s = 0.f;
#pragma unroll 8
        for (int t = 0; t < 64; t++) s += sp[(size_t)t * 4096];
        float z = __ldg(g_zs + b * 128 + (((idx >> 10) << 5) | ((idx >> 5) & 31)));
        g_ctx[(size_t)b * 4096 + idx] = s / z;
    }
}

// ---------------------------------------------------------------------------
// Kernel 3: M_b = Wout∘ctx as bf16 hi/lo.  grid = (32, 8 o-slices).
// ---------------------------------------------------------------------------
__global__ void __launch_bounds__(256) k_M(const float* __restrict__ Wout) {
    __shared__ float ctxs[4 * 32 * 33];
    const int b = blockIdx.x;
    const int og = blockIdx.y;
    const int tid = threadIdx.x;
#pragma unroll
    for (int s2 = 0; s2 < 16; s2++) {
        int idx = tid + s2 * 256;
        int h = idx >> 10, d = (idx >> 5) & 31, e = idx & 31;
        ctxs[h * 1056 + d * 33 + e] = g_ctx[(size_t)b * 4096 + idx];
    }
    __syncthreads();
    unsigned short* Mh = g_Mbh + (size_t)b * 16384;
    unsigned short* Ml = g_Mbl + (size_t)b * 16384;
#pragma unroll
    for (int s8 = 0; s8 < 8; s8++) {
        int pidx = og * 2048 + tid + s8 * 256;
        int o = pidx >> 7, hd = pidx & 127;
        int h = hd >> 5, dd = hd & 31;
        const float* wrow = Wout + o * 128 + h * 32;
        const float* crow = ctxs + h * 1056 + dd * 33;
        float s = 0.f;
#pragma unroll
        for (int e = 0; e < 32; e++) s += __ldg(wrow + e) * crow[e];
        __nv_bfloat16 hb = __float2bfloat16(s);
        float hf = __bfloat162float(hb);
        Mh[pidx] = __bfloat16_as_ushort(hb);
        Ml[pidx] = __bfloat16_as_ushort(__float2bfloat16(s - hf));
    }
}

// ---------------------------------------------------------------------------
// Kernel 4: out = LayerNorm( M_b @ softmax_d(q) + bout ); q pre-exp'd.
// M_b prefetched via cp.async.  grid = (64 n-tiles, 32 batches)
// ---------------------------------------------------------------------------
#define SMEM_K4 107008
__global__ void __launch_bounds__(256) k_out(const float* __restrict__ bout,
                                             const float* __restrict__ lnw,
                                             const float* __restrict__ lnb,
                                             float* __restrict__ out) {
    extern __shared__ char sm[];
    const u32 sbase = (u32)__cvta_generic_to_shared(sm);
    const u32 oBh = 0, oBl = 17408, oAh = 34816, oAl = 69632;
    float* stage = (float*)(sm + oAh);
    float* ssum  = (float*)(sm + 104448);
    float* red   = (float*)(sm + 105472);
    float* meanv = (float*)(sm + 106496);
    float* rstd  = (float*)(sm + 106752);
    const int t = blockIdx.x, b = blockIdx.y;
    const int tid = threadIdx.x;
    const float* qb = g_q + (size_t)b * CDIM * NSP + t * 64;

    {
        const uint4* gl = (const uint4*)(g_Mbl + (size_t)b * 16384);
#pragma unroll
        for (int it = 0; it < 8; it++) {
            int u = tid + it * 256;
            int r = u >> 4, c = u & 15;
            CPA16(sbase + oAl + r * 272 + c * 16, gl + u);
        }
        CPA_COMMIT();
    }

#pragma unroll
    for (int it = 0; it < 8; it++) {
        int u = tid + it * 256;
        int k = u >> 4, nc = (u & 15) << 2;
        float4 v = *(const float4*)(qb + (size_t)k * NSP + nc);
        *(float4*)(stage + k * 68 + nc) = v;
    }
    __syncthreads();

    {
        int n = tid & 63, hh = tid >> 6;
        float s = 0.f;
#pragma unroll
        for (int kk = 0; kk < 32; kk++) s += stage[(hh * 32 + kk) * 68 + n];
        ssum[hh * 64 + n] = 1.f / s;
    }
    __syncthreads();

#pragma unroll
    for (int it = 0; it < 4; it++) {
        int v = tid + it * 256;
        int n = v & 63, k8 = v >> 6;
        float rn_ = ssum[(k8 >> 2) * 64 + n];
        u32 hw[4], lw[4];
#pragma unroll
        for (int jj = 0; jj < 2; jj++) {
            float4 q4;
            q4.x = stage[(k8 * 8 + 4 * jj + 0) * 68 + n] * rn_;
            q4.y = stage[(k8 * 8 + 4 * jj + 1) * 68 + n] * rn_;
            q4.z = stage[(k8 * 8 + 4 * jj + 2) * 68 + n] * rn_;
            q4.w = stage[(k8 * 8 + 4 * jj + 3) * 68 + n] * rn_;
            split4(q4, hw[2 * jj], hw[2 * jj + 1], lw[2 * jj], lw[2 * jj + 1]);
        }
        u32 off = n * 272 + k8 * 16;
        *(uint4*)(sm + oBh + off) = make_uint4(hw[0], hw[1], hw[2], hw[3]);
        *(uint4*)(sm + oBl + off) = make_uint4(lw[0], lw[1], lw[2], lw[3]);
    }
    __syncthreads();

    {
        const uint4* gh = (const uint4*)(g_Mbh + (size_t)b * 16384);
#pragma unroll
        for (int it = 0; it < 8; it++) {
            int u = tid + it * 256;
            int r = u >> 4, c = u & 15;
            CPA16(sbase + oAh + r * 272 + c * 16, gh + u);
        }
        CPA_COMMIT();
        CPA_WAIT0();
    }
    __syncthreads();

    const int l = tid & 31, wid = tid >> 5;
    const int wm = (wid & 3) * 32;
    const int nh = (wid >> 2) * 32;
    const u32 aoff = (u32)((wm + (l & 15)) * 272 + (l >> 4) * 16);
    const u32 boff = (u32)((nh + (l & 7) + ((l >> 4) << 3)) * 272 + (((l >> 3) & 1) << 4));

    float acc[2][4][4];
#pragma unroll
    for (int mt = 0; mt < 2; mt++)
#pragma unroll
        for (int nt = 0; nt < 4; nt++)
#pragma unroll
            for (int q = 0; q < 4; q++) acc[mt][nt][q] = 0.f;

#pragma unroll
    for (int kc = 0; kc < 8; kc++) {
        u32 ah[2][4], al_[2][4], bhf[2][4], blf[2][4];
#pragma unroll
        for (int mt = 0; mt < 2; mt++) {
            u32 o = aoff + mt * (16 * 272) + kc * 32;
            ldm4(ah[mt],  sbase + oAh + o);
            ldm4(al_[mt], sbase + oAl + o);
        }
#pragma unroll
        for (int p = 0; p < 2; p++) {
            u32 o = boff + p * (16 * 272) + kc * 32;
            ldm4(bhf[p], sbase + oBh + o);
            ldm4(blf[p], sbase + oBl + o);
        }
#pragma unroll
        for (int mt = 0; mt < 2; mt++)
#pragma unroll
            for (int nt = 0; nt < 4; nt++) {
                int p = nt >> 1, q = (nt & 1) * 2;
                mma16816(acc[mt][nt], ah[mt],  bhf[p][q], bhf[p][q + 1]);
                mma16816(acc[mt][nt], al_[mt], bhf[p][q], bhf[p][q + 1]);
                mma16816(acc[mt][nt], ah[mt],  blf[p][q], blf[p][q + 1]);
            }
    }

#pragma unroll
    for (int mt = 0; mt < 2; mt++)
#pragma unroll
        for (int rh = 0; rh < 2; rh++) {
            float bo = __ldg(bout + wm + mt * 16 + (l >> 2) + rh * 8);
#pragma unroll
            for (int nt = 0; nt < 4; nt++) {
                acc[mt][nt][rh * 2 + 0] += bo;
                acc[mt][nt][rh * 2 + 1] += bo;
            }
        }

#pragma unroll
    for (int q = 0; q < 2; q++) {
#pragma unroll
        for (int nt = 0; nt < 4; nt++) {
            float cs = acc[0][nt][q] + acc[0][nt][2 + q] + acc[1][nt][q] + acc[1][nt][2 + q];
            cs += __shfl_xor_sync(0xffffffffu, cs, 4);
            cs += __shfl_xor_sync(0xffffffffu, cs, 8);
            cs += __shfl_xor_sync(0xffffffffu, cs, 16);
            if (l < 4) red[(wid & 3) * 64 + nh + nt * 8 + l * 2 + q] = cs;
        }
    }
    __syncthreads();
    if (tid < 64) {
        float s = red[tid] + red[64 + tid] + red[128 + tid] + red[192 + tid];
        meanv[tid] = s * (1.f / 128.f);
    }
    __syncthreads();
#pragma unroll
    for (int q = 0; q < 2; q++) {
#pragma unroll
        for (int nt = 0; nt < 4; nt++) {
            float cm = meanv[nh + nt * 8 + (l & 3) * 2 + q];
            float d0 = acc[0][nt][q] - cm, d1 = acc[0][nt][2 + q] - cm;
            float d2 = acc[1][nt][q] - cm, d3 = acc[1][nt][2 + q] - cm;
            float cs = d0 * d0 + d1 * d1 + d2 * d2 + d3 * d3;
            cs += __shfl_xor_sync(0xffffffffu, cs, 4);
            cs += __shfl_xor_sync(0xffffffffu, cs, 8);
            cs += __shfl_xor_sync(0xffffffffu, cs, 16);
            if (l < 4) red[(wid & 3) * 64 + nh + nt * 8 + l * 2 + q] = cs;
        }
    }
    __syncthreads();
    if (tid < 64) {
        float s = red[tid] + red[64 + tid] + red[128 + tid] + red[192 + tid];
        rstd[tid] = rsqrtf(s * (1.f / 128.f) + EPS);
    }
    __syncthreads();

#pragma unroll
    for (int mt = 0; mt < 2; mt++)
#pragma unroll
        for (int rh = 0; rh < 2; rh++) {
            int row = wm + mt * 16 + (l >> 2) + rh * 8;
            float lw = __ldg(lnw + row);
            float lb = __ldg(lnb + row);
#pragma unroll
            for (int nt = 0; nt < 4; nt++) {
                int col = nh + nt * 8 + (l & 3) * 2;
                float m0 = meanv[col], m1 = meanv[col + 1];
                float r0 = rstd[col], r1 = rstd[col + 1];
                float2 o2;
                o2.x = (acc[mt][nt][rh * 2 + 0] - m0) * r0 * lw + lb;
                o2.y = (acc[mt][nt][rh * 2 + 1] - m1) * r1 * lw + lb;
                *(float2*)(out + ((size_t)b * CDIM + row) * NSP + t * 64 + col) = o2;
            }
        }
}

// ---------------------------------------------------------------------------
extern "C" void kernel_launch(void* const* d_in, const int* in_sizes, int n_in,
                              void* d_out, int out_size) {
    const float* x    = (const float*)d_in[0];
    const float* Wqkv = (const float*)d_in[1];
    const float* Wout = (const float*)d_in[2];
    const float* bout = (const float*)d_in[3];
    const float* lnw  = (const float*)d_in[4];
    const float* lnb  = (const float*)d_in[5];
    float* out = (float*)d_out;

    cudaFuncSetAttribute(k_gemm_qkv, cudaFuncAttributeMaxDynamicSharedMemorySize, SMEM_K1);
    cudaFuncSetAttribute(k_out, cudaFuncAttributeMaxDynamicSharedMemorySize, SMEM_K4);

    k_splitW<<<48, 256>>>(Wqkv);
    k_gemm_qkv<<<dim3(64, B), 256, SMEM_K1>>>(x);
    k_z<<<B, 256>>>();
    k_ctx<<<dim3(B, 8), 256>>>();
    k_M<<<dim3(B, 8), 256>>>(Wout);
    k_out<<<dim3(64, B), 256, SMEM_K4>>>(bout, lnw, lnb, out);
}